// round 2
// baseline (speedup 1.0000x reference)
#include <cuda_runtime.h>

#define GG 128
#define G3 (GG * GG * GG)
#define NCASC 5
#define MAXCAMS 32
#define CC_STRIDE 48  // floats per camera constant block (44 used, padded to 12 float4)

// Per-cam constants, written by precompute kernel:
// [0..8]   M = K @ R^T (row-major 3x3)
// [9..13]  gates: Amin, Bmax, Cmin, Dmax, Fmin  (union over cascades)
// [14..43] thresholds per cascade c: A,B,C,D,E,F at 14+6c
__device__ float g_cc[MAXCAMS * CC_STRIDE];
__device__ float g_WH[2];

__device__ __forceinline__ unsigned compact3(unsigned x) {
    x &= 0x49249249u;
    x = (x | (x >> 2))  & 0xC30C30C3u;
    x = (x | (x >> 4))  & 0x0F00F00Fu;
    x = (x | (x >> 8))  & 0xFF0000FFu;
    x = (x | (x >> 16)) & 0x000003FFu;
    return x;
}

__global__ void precompute_kernel(const float* __restrict__ K,
                                  const float* __restrict__ poses,
                                  const int* __restrict__ scale_p,
                                  const int* __restrict__ wp,
                                  const int* __restrict__ hp,
                                  int n_cams)
{
    int n = threadIdx.x;
    if (n == 0) { g_WH[0] = (float)(*wp); g_WH[1] = (float)(*hp); }
    if (n >= n_cams) return;

    const float fx = K[0], cx = K[2], fy = K[4], cy = K[5];
    const float W = (float)(*wp), H = (float)(*hp);
    const float scal = (float)(*scale_p);

    const float* P = poses + n * 12;
    float R[3][3], t[3];
#pragma unroll
    for (int r = 0; r < 3; r++) {
#pragma unroll
        for (int c = 0; c < 3; c++) R[r][c] = P[r * 4 + c];
        t[r] = P[r * 4 + 3];
    }
    // w2c: R' = R^T, T' = -R^T t
    float Tp[3];
#pragma unroll
    for (int i = 0; i < 3; i++)
        Tp[i] = -(R[0][i] * t[0] + R[1][i] * t[1] + R[2][i] * t[2]);

    float* cc = g_cc + n * CC_STRIDE;
#pragma unroll
    for (int j = 0; j < 3; j++) {
        cc[0 + j] = fx * R[j][0] + cx * R[j][2];  // M row 0
        cc[3 + j] = fy * R[j][1] + cy * R[j][2];  // M row 1
        cc[6 + j] = R[j][2];                      // M row 2
    }
    const float q0 = fx * Tp[0] + cx * Tp[2];
    const float q1 = fy * Tp[1] + cy * Tp[2];
    const float q2 = Tp[2];

    float Amin = 3.4e38f, Bmax = -3.4e38f, Cmin = 3.4e38f, Dmax = -3.4e38f, Fmin = 3.4e38f;
    for (int c = 0; c < NCASC; c++) {
        float s  = fminf(exp2f((float)(c - 1)), scal);
        float se = s - s / (float)GG;
        double ds = (double)se;
        // u' >= 0        <=> p0 >= A
        // u' <  W*d      <=> r0 <  B   (r0 = p0 - W*p2)
        // v' >= 0        <=> p1 >= C
        // v' <  H*d      <=> r1 <  D
        // d  >= NEAR     <=> p2 >= E
        // d  >  0        <=> p2 >  F
        float A = (float)(-(double)q0 / ds);
        float B = (float)(((double)W * (double)q2 - (double)q0) / ds);
        float C = (float)(-(double)q1 / ds);
        float D = (float)(((double)H * (double)q2 - (double)q1) / ds);
        float E = (float)(((double)0.01f - (double)q2) / ds);
        float F = (float)(-(double)q2 / ds);
        float* T = cc + 14 + 6 * c;
        T[0] = A; T[1] = B; T[2] = C; T[3] = D; T[4] = E; T[5] = F;
        Amin = fminf(Amin, A); Bmax = fmaxf(Bmax, B);
        Cmin = fminf(Cmin, C); Dmax = fmaxf(Dmax, D);
        Fmin = fminf(Fmin, F);
    }
    cc[9]  = Amin; cc[10] = Bmax; cc[11] = Cmin; cc[12] = Dmax; cc[13] = Fmin;
    cc[44] = 0.f; cc[45] = 0.f; cc[46] = 0.f; cc[47] = 0.f;
}

__global__ void __launch_bounds__(256, 2)
grid_kernel(float* __restrict__ out, int n_cams)
{
    __shared__ float s_cc[MAXCAMS * CC_STRIDE];
    {
        int nfl = n_cams * CC_STRIDE;
        for (int i = threadIdx.x; i < nfl; i += blockDim.x) s_cc[i] = g_cc[i];
    }
    __syncthreads();
    const float W = g_WH[0], H = g_WH[1];

    // Each thread owns 8 consecutive Morton indices = an aligned 2x2x2 spatial block.
    const unsigned base = (blockIdx.x * blockDim.x + threadIdx.x) * 8u;
    const unsigned ib = compact3(base);
    const unsigned jb = compact3(base >> 1);
    const unsigned kb = compact3(base >> 2);

    float xs[2], ys[2], zs[2];
#pragma unroll
    for (int d = 0; d < 2; d++) {
        // match reference: coords/(G-1)*2 - 1 with true fp32 division
        xs[d] = __fdiv_rn((float)(ib + d), (float)(GG - 1)) * 2.0f - 1.0f;
        ys[d] = __fdiv_rn((float)(jb + d), (float)(GG - 1)) * 2.0f - 1.0f;
        zs[d] = __fdiv_rn((float)(kb + d), (float)(GG - 1)) * 2.0f - 1.0f;
    }

    // acc[cell]: bits [5c..5c+4] = covered count for cascade c (<=16 fits 5 bits),
    //            bit  [25+c]     = too-near-any flag for cascade c
    unsigned acc[8];
#pragma unroll
    for (int i = 0; i < 8; i++) acc[i] = 0u;

    for (int n = 0; n < n_cams; n++) {
        float4 ccv[11];
        const float4* src4 = (const float4*)(s_cc + n * CC_STRIDE);
#pragma unroll
        for (int i = 0; i < 11; i++) ccv[i] = src4[i];
        const float* cc = (const float*)ccv;

#pragma unroll
        for (int cell = 0; cell < 8; cell++) {
            const float x = xs[cell & 1];
            const float y = ys[(cell >> 1) & 1];
            const float z = zs[(cell >> 2) & 1];
            const float p0 = fmaf(cc[2], z, fmaf(cc[1], y, cc[0] * x));
            const float p1 = fmaf(cc[5], z, fmaf(cc[4], y, cc[3] * x));
            const float p2 = fmaf(cc[8], z, fmaf(cc[7], y, cc[6] * x));
            const float r0 = fmaf(-W, p2, p0);
            const float r1 = fmaf(-H, p2, p1);

            // union-over-cascades gate: skip this cam entirely for this cell if
            // no cascade can possibly mark it covered or too-near
            bool g = (p0 >= cc[9]) & (r0 < cc[10]) & (p1 >= cc[11]) &
                     (r1 < cc[12]) & (p2 > cc[13]);
            if (g) {
#pragma unroll
                for (int c = 0; c < NCASC; c++) {
                    const float A = cc[14 + 6 * c], B = cc[15 + 6 * c];
                    const float C = cc[16 + 6 * c], D = cc[17 + 6 * c];
                    const float E = cc[18 + 6 * c], F = cc[19 + 6 * c];
                    bool i4 = (p0 >= A) & (r0 < B) & (p1 >= C) & (r1 < D);
                    if (i4 & (p2 >= E)) acc[cell] += (1u << (5 * c));
                    if (i4 & (p2 < E) & (p2 > F)) acc[cell] |= (1u << (25 + c));
                }
            }
        }
    }

    const float invN = __fdiv_rn(1.0f, (float)n_cams);
    float* outg = out;                       // grid:  cascades 0..4
    float* outc = out + (size_t)NCASC * G3;  // count: cascades 0..4

#pragma unroll
    for (int c = 0; c < NCASC; c++) {
        float gv[8], cv[8];
#pragma unroll
        for (int cell = 0; cell < 8; cell++) {
            unsigned cnt  = (acc[cell] >> (5 * c)) & 31u;
            unsigned nearf = (acc[cell] >> (25 + c)) & 1u;
            cv[cell] = (float)cnt * invN;
            gv[cell] = (cnt > 0u && nearf == 0u) ? 0.0f : -1.0f;
        }
        size_t off = (size_t)c * G3 + base;
        float4* pg = (float4*)(outg + off);
        pg[0] = make_float4(gv[0], gv[1], gv[2], gv[3]);
        pg[1] = make_float4(gv[4], gv[5], gv[6], gv[7]);
        float4* pc = (float4*)(outc + off);
        pc[0] = make_float4(cv[0], cv[1], cv[2], cv[3]);
        pc[1] = make_float4(cv[4], cv[5], cv[6], cv[7]);
    }
}

extern "C" void kernel_launch(void* const* d_in, const int* in_sizes, int n_in,
                              void* d_out, int out_size)
{
    const float* K     = (const float*)d_in[0];
    const float* poses = (const float*)d_in[1];
    const int*   sc    = (const int*)d_in[3];
    const int*   wp    = (const int*)d_in[4];
    const int*   hp    = (const int*)d_in[5];

    int n_cams = in_sizes[1] / 12;
    if (n_cams > MAXCAMS) n_cams = MAXCAMS;

    precompute_kernel<<<1, 32>>>(K, poses, sc, wp, hp, n_cams);

    const int threads = 256;
    const int blocks = (G3 / 8) / threads;  // 1024
    grid_kernel<<<blocks, threads>>>((float*)d_out, n_cams);
}

// round 3
// speedup vs baseline: 1.4784x; 1.4784x over previous
#include <cuda_runtime.h>

#define GG 128
#define G3 (GG * GG * GG)
#define NCASC 5
#define MAXCAMS 32
#define C4 24  // float4 per camera constant block

// Per-cam constants (float4 units), written by precompute kernel:
// [0] = (M00,M01,M02, gateA)   gateA = Amin - rad0
// [1] = (M10,M11,M12, gateC)   gateC = Cmin - rad1
// [2] = (M20,M21,M22, gateF)   gateF = Fmin - rad2
// [3] = (gateB, gateD, W, H)   gateB = Bmax + rad3, gateD = Dmax + rad4
// per cascade c (base = 4+4c):
// [base+0] = (A, B, C, D)          exact thresholds (per-cell path)
// [base+1] = (E, F, E_in, F_out)
// [base+2] = (A_in, B_in, C_in, D_in)
// [base+3] = (A_out, B_out, C_out, D_out)
__device__ float4 g_cc[MAXCAMS * C4];
__device__ float g_WH[2];

__device__ __forceinline__ unsigned compact3(unsigned x) {
    x &= 0x49249249u;
    x = (x | (x >> 2))  & 0xC30C30C3u;
    x = (x | (x >> 4))  & 0x0F00F00Fu;
    x = (x | (x >> 8))  & 0xFF0000FFu;
    x = (x | (x >> 16)) & 0x000003FFu;
    return x;
}

__global__ void precompute_kernel(const float* __restrict__ K,
                                  const float* __restrict__ poses,
                                  const int* __restrict__ scale_p,
                                  const int* __restrict__ wp,
                                  const int* __restrict__ hp,
                                  int n_cams)
{
    int n = threadIdx.x;
    if (n == 0) { g_WH[0] = (float)(*wp); g_WH[1] = (float)(*hp); }
    if (n >= n_cams) return;

    const double fx = K[0], cx = K[2], fy = K[4], cy = K[5];
    const double W = (double)(*wp), H = (double)(*hp);
    const double scal = (double)(*scale_p);

    const float* P = poses + n * 12;
    double R[3][3], t[3];
#pragma unroll
    for (int r = 0; r < 3; r++) {
#pragma unroll
        for (int c = 0; c < 3; c++) R[r][c] = (double)P[r * 4 + c];
        t[r] = (double)P[r * 4 + 3];
    }
    double Tp[3];
#pragma unroll
    for (int i = 0; i < 3; i++)
        Tp[i] = -(R[0][i] * t[0] + R[1][i] * t[1] + R[2][i] * t[2]);

    double M0[3], M1[3], M2[3];
#pragma unroll
    for (int j = 0; j < 3; j++) {
        M0[j] = fx * R[j][0] + cx * R[j][2];
        M1[j] = fy * R[j][1] + cy * R[j][2];
        M2[j] = R[j][2];
    }
    const double q0 = fx * Tp[0] + cx * Tp[2];
    const double q1 = fy * Tp[1] + cy * Tp[2];
    const double q2 = Tp[2];

    // interval radii over a 2x2x2 cell block (half-extent h per axis),
    // inflated to stay conservative vs fp32 per-cell evaluation
    const double h = 1.0 / (double)(GG - 1);
    const double INFL = 1.0005, EPSA = 0.03;
    double rad0 = (fabs(M0[0]) + fabs(M0[1]) + fabs(M0[2])) * h * INFL + EPSA;
    double rad1 = (fabs(M1[0]) + fabs(M1[1]) + fabs(M1[2])) * h * INFL + EPSA;
    double rad2 = (fabs(M2[0]) + fabs(M2[1]) + fabs(M2[2])) * h * INFL + EPSA;
    double rad3 = (fabs(M0[0] - W * M2[0]) + fabs(M0[1] - W * M2[1]) +
                   fabs(M0[2] - W * M2[2])) * h * INFL + EPSA;
    double rad4 = (fabs(M1[0] - H * M2[0]) + fabs(M1[1] - H * M2[1]) +
                   fabs(M1[2] - H * M2[2])) * h * INFL + EPSA;

    float4* cc = g_cc + n * C4;

    double Amin = 1e300, Bmax = -1e300, Cmin = 1e300, Dmax = -1e300, Fmin = 1e300;
#pragma unroll
    for (int c = 0; c < NCASC; c++) {
        double s  = exp2((double)(c - 1));
        if (s > scal) s = scal;
        double se = s - s / (double)GG;
        // covered: p0>=A & r0<B & p1>=C & r1<D & p2>=E ; near adds p2<E & p2>F
        double A = -q0 / se;
        double B = (W * q2 - q0) / se;
        double C = -q1 / se;
        double D = (H * q2 - q1) / se;
        double E = ((double)0.01f - q2) / se;
        double F = -q2 / se;
        cc[4 + 4 * c + 0] = make_float4((float)A, (float)B, (float)C, (float)D);
        cc[4 + 4 * c + 1] = make_float4((float)E, (float)F,
                                        (float)(E + rad2), (float)(F - rad2));
        cc[4 + 4 * c + 2] = make_float4((float)(A + rad0), (float)(B - rad3),
                                        (float)(C + rad1), (float)(D - rad4));
        cc[4 + 4 * c + 3] = make_float4((float)(A - rad0), (float)(B + rad3),
                                        (float)(C - rad1), (float)(D + rad4));
        Amin = fmin(Amin, A); Bmax = fmax(Bmax, B);
        Cmin = fmin(Cmin, C); Dmax = fmax(Dmax, D);
        Fmin = fmin(Fmin, F);
    }
    cc[0] = make_float4((float)M0[0], (float)M0[1], (float)M0[2], (float)(Amin - rad0));
    cc[1] = make_float4((float)M1[0], (float)M1[1], (float)M1[2], (float)(Cmin - rad1));
    cc[2] = make_float4((float)M2[0], (float)M2[1], (float)M2[2], (float)(Fmin - rad2));
    cc[3] = make_float4((float)(Bmax + rad3), (float)(Dmax + rad4), (float)W, (float)H);
}

__global__ void __launch_bounds__(256, 3)
grid_kernel(float* __restrict__ out, int n_cams)
{
    __shared__ float4 s_cc[MAXCAMS * C4];
    {
        int nf = n_cams * C4;
        for (int i = threadIdx.x; i < nf; i += blockDim.x) s_cc[i] = g_cc[i];
    }
    __syncthreads();
    const float W = g_WH[0], H = g_WH[1];

    // Each thread owns 8 consecutive Morton indices = an aligned 2x2x2 spatial block.
    const unsigned base = (blockIdx.x * blockDim.x + threadIdx.x) * 8u;
    const unsigned ib = compact3(base);
    const unsigned jb = compact3(base >> 1);
    const unsigned kb = compact3(base >> 2);

    float xs[2], ys[2], zs[2];
#pragma unroll
    for (int d = 0; d < 2; d++) {
        xs[d] = __fdiv_rn((float)(ib + d), (float)(GG - 1)) * 2.0f - 1.0f;
        ys[d] = __fdiv_rn((float)(jb + d), (float)(GG - 1)) * 2.0f - 1.0f;
        zs[d] = __fdiv_rn((float)(kb + d), (float)(GG - 1)) * 2.0f - 1.0f;
    }
    const float xc = 0.5f * (xs[0] + xs[1]);
    const float yc = 0.5f * (ys[0] + ys[1]);
    const float zc = 0.5f * (zs[0] + zs[1]);

    // acc[cell]: bits [5c..5c+4] per-cell covered count (boundary cams),
    //            bit [25+c] too-near flag. cntAll: block-wide covered counts.
    unsigned acc[8];
#pragma unroll
    for (int i = 0; i < 8; i++) acc[i] = 0u;
    unsigned cntAll = 0u;

    for (int n = 0; n < n_cams; n++) {
        const float4* c4 = s_cc + n * C4;
        const float4 m0 = c4[0], m1 = c4[1], m2 = c4[2], gg = c4[3];

        const float p0 = fmaf(m0.z, zc, fmaf(m0.y, yc, m0.x * xc));
        const float p1 = fmaf(m1.z, zc, fmaf(m1.y, yc, m1.x * xc));
        const float p2 = fmaf(m2.z, zc, fmaf(m2.y, yc, m2.x * xc));
        const float r0 = fmaf(-W, p2, p0);
        const float r1 = fmaf(-H, p2, p1);

        // union-over-cascades block gate (conservative)
        bool g = (p0 >= m0.w) & (p1 >= m1.w) & (p2 > m2.w) &
                 (r0 < gg.x) & (r1 < gg.y);
        if (!g) continue;

        unsigned bmask = 0u;
#pragma unroll
        for (int c = 0; c < NCASC; c++) {
            const float4 vef  = c4[4 + 4 * c + 1];
            const float4 vin  = c4[4 + 4 * c + 2];
            const float4 vout = c4[4 + 4 * c + 3];
            bool allin  = (p0 >= vin.x) & (r0 < vin.y) & (p1 >= vin.z) &
                          (r1 < vin.w) & (p2 >= vef.z);
            bool allout = (p0 < vout.x) | (r0 >= vout.y) | (p1 < vout.z) |
                          (r1 >= vout.w) | (p2 <= vef.w);
            if (allin) cntAll += (1u << (5 * c));
            else if (!allout) bmask |= (1u << c);
        }

        // boundary cascades: exact per-cell path (identical math to reference)
        while (bmask) {
            const int c = __ffs(bmask) - 1;
            bmask &= bmask - 1;
            const float4 v0  = c4[4 + 4 * c + 0];
            const float4 vef = c4[4 + 4 * c + 1];
            const unsigned covbit = 1u << (5 * c);
            const unsigned nearbit = 1u << (25 + c);
#pragma unroll
            for (int cell = 0; cell < 8; cell++) {
                const float x = xs[cell & 1];
                const float y = ys[(cell >> 1) & 1];
                const float z = zs[(cell >> 2) & 1];
                const float P0 = fmaf(m0.z, z, fmaf(m0.y, y, m0.x * x));
                const float P1 = fmaf(m1.z, z, fmaf(m1.y, y, m1.x * x));
                const float P2 = fmaf(m2.z, z, fmaf(m2.y, y, m2.x * x));
                const float R0 = fmaf(-W, P2, P0);
                const float R1 = fmaf(-H, P2, P1);
                bool i4 = (P0 >= v0.x) & (R0 < v0.y) & (P1 >= v0.z) & (R1 < v0.w);
                if (i4 & (P2 >= vef.x)) acc[cell] += covbit;
                if (i4 & (P2 < vef.x) & (P2 > vef.y)) acc[cell] |= nearbit;
            }
        }
    }

    const float invN = __fdiv_rn(1.0f, (float)n_cams);
    float* outg = out;                       // grid:  cascades 0..4
    float* outc = out + (size_t)NCASC * G3;  // count: cascades 0..4

#pragma unroll
    for (int c = 0; c < NCASC; c++) {
        const unsigned allc = (cntAll >> (5 * c)) & 31u;
        float gv[8], cv[8];
#pragma unroll
        for (int cell = 0; cell < 8; cell++) {
            unsigned cnt   = ((acc[cell] >> (5 * c)) & 31u) + allc;
            unsigned nearf = (acc[cell] >> (25 + c)) & 1u;
            cv[cell] = (float)cnt * invN;
            gv[cell] = (cnt > 0u && nearf == 0u) ? 0.0f : -1.0f;
        }
        size_t off = (size_t)c * G3 + base;
        float4* pg = (float4*)(outg + off);
        pg[0] = make_float4(gv[0], gv[1], gv[2], gv[3]);
        pg[1] = make_float4(gv[4], gv[5], gv[6], gv[7]);
        float4* pc = (float4*)(outc + off);
        pc[0] = make_float4(cv[0], cv[1], cv[2], cv[3]);
        pc[1] = make_float4(cv[4], cv[5], cv[6], cv[7]);
    }
}

extern "C" void kernel_launch(void* const* d_in, const int* in_sizes, int n_in,
                              void* d_out, int out_size)
{
    const float* K     = (const float*)d_in[0];
    const float* poses = (const float*)d_in[1];
    const int*   sc    = (const int*)d_in[3];
    const int*   wp    = (const int*)d_in[4];
    const int*   hp    = (const int*)d_in[5];

    int n_cams = in_sizes[1] / 12;
    if (n_cams > MAXCAMS) n_cams = MAXCAMS;

    precompute_kernel<<<1, 32>>>(K, poses, sc, wp, hp, n_cams);

    const int threads = 256;
    const int blocks = (G3 / 8) / threads;  // 1024
    grid_kernel<<<blocks, threads>>>((float*)d_out, n_cams);
}

// round 7
// speedup vs baseline: 2.3820x; 1.6113x over previous
#include <cuda_runtime.h>

#define GG 128
#define G3 (GG * GG * GG)
#define NCASC 5
#define MAXCAMS 32
#define C4 24  // float4 per camera constant block

// Per-cam constants (float4 units) in shared memory, built in-kernel:
// [0] = (M00,M01,M02, rad0t)   thread-level interval radii in .w
// [1] = (M10,M11,M12, rad1t)
// [2] = (M20,M21,M22, rad2t)
// [3] = (rad3t, rad4t, W, H)
// per cascade c (base = 4+4c):
// [base+0] = (A, B, C, D)      exact thresholds (per-cell path)
// [base+1] = (E, F, E_in, F_out)
// [base+2] = (A_in, B_in, C_in, D_in)    thread-level all-in
// [base+3] = (A_out, B_out, C_out, D_out) thread-level all-out

__device__ __forceinline__ unsigned compact3(unsigned x) {
    x &= 0x49249249u;
    x = (x | (x >> 2))  & 0xC30C30C3u;
    x = (x | (x >> 4))  & 0x0F00F00Fu;
    x = (x | (x >> 8))  & 0xFF0000FFu;
    x = (x | (x >> 16)) & 0x000003FFu;
    return x;
}

__global__ void __launch_bounds__(256, 3)
grid_kernel(float* __restrict__ out,
            const float* __restrict__ K,
            const float* __restrict__ poses,
            const int* __restrict__ scale_p,
            const int* __restrict__ wp,
            const int* __restrict__ hp,
            int n_cams)
{
    __shared__ float4 s_cc[MAXCAMS * C4];
    __shared__ int s_allin[NCASC];
    __shared__ int s_bnd[MAXCAMS];
    __shared__ int s_camList[MAXCAMS];
    __shared__ int s_nBnd;

    const int tid = threadIdx.x;
    if (tid < NCASC) s_allin[tid] = 0;
    if (tid < MAXCAMS) s_bnd[tid] = 0;

    // ---- Phase 1: per-cam constant precompute (fp32, one thread per cam) ----
    if (tid < n_cams) {
        const float fx = K[0], cx = K[2], fy = K[4], cy = K[5];
        const float W = (float)(*wp), H = (float)(*hp);
        const float scal = (float)(*scale_p);

        const float* P = poses + tid * 12;
        const float R00 = P[0], R01 = P[1], R02 = P[2],  t0 = P[3];
        const float R10 = P[4], R11 = P[5], R12 = P[6],  t1 = P[7];
        const float R20 = P[8], R21 = P[9], R22 = P[10], t2 = P[11];
        // T' = -R^T t
        const float Tp0 = -(R00 * t0 + R10 * t1 + R20 * t2);
        const float Tp1 = -(R01 * t0 + R11 * t1 + R21 * t2);
        const float Tp2 = -(R02 * t0 + R12 * t1 + R22 * t2);
        // M = K @ R^T rows
        const float M00 = fx * R00 + cx * R02, M01 = fx * R10 + cx * R12, M02 = fx * R20 + cx * R22;
        const float M10 = fy * R01 + cy * R02, M11 = fy * R11 + cy * R12, M12 = fy * R21 + cy * R22;
        const float M20 = R02, M21 = R12, M22 = R22;
        const float q0 = fx * Tp0 + cx * Tp2;
        const float q1 = fy * Tp1 + cy * Tp2;
        const float q2 = Tp2;

        // thread-level (2x2x2 block) interval radii, conservative
        const float h = 1.0f / (float)(GG - 1);
        const float INFL = 1.001f, EPSA = 0.03f;
        const float rad0 = (fabsf(M00) + fabsf(M01) + fabsf(M02)) * h * INFL + EPSA;
        const float rad1 = (fabsf(M10) + fabsf(M11) + fabsf(M12)) * h * INFL + EPSA;
        const float rad2 = (fabsf(M20) + fabsf(M21) + fabsf(M22)) * h * INFL + EPSA;
        const float rad3 = (fabsf(M00 - W * M20) + fabsf(M01 - W * M21) +
                            fabsf(M02 - W * M22)) * h * INFL + EPSA;
        const float rad4 = (fabsf(M10 - H * M20) + fabsf(M11 - H * M21) +
                            fabsf(M12 - H * M22)) * h * INFL + EPSA;

        float4* cc = s_cc + tid * C4;
        cc[0] = make_float4(M00, M01, M02, rad0);
        cc[1] = make_float4(M10, M11, M12, rad1);
        cc[2] = make_float4(M20, M21, M22, rad2);
        cc[3] = make_float4(rad3, rad4, W, H);

#pragma unroll
        for (int c = 0; c < NCASC; c++) {
            float s = fminf(exp2f((float)(c - 1)), scal);
            float se = s - s * (1.0f / (float)GG);   // exact: powers of two
            float inv = __fdiv_rn(1.0f, se);
            float A = -q0 * inv;
            float B = (W * q2 - q0) * inv;
            float C = -q1 * inv;
            float D = (H * q2 - q1) * inv;
            float E = (0.01f - q2) * inv;
            float F = -q2 * inv;
            cc[4 + 4 * c + 0] = make_float4(A, B, C, D);
            cc[4 + 4 * c + 1] = make_float4(E, F, E + rad2, F - rad2);
            cc[4 + 4 * c + 2] = make_float4(A + rad0, B - rad3, C + rad1, D - rad4);
            cc[4 + 4 * c + 3] = make_float4(A - rad0, B + rad3, C - rad1, D + rad4);
        }
    }
    __syncthreads();

    // ---- Phase 2: CTA-level classification (region = 16x16x8 cells) ----
    const unsigned baseCTA = blockIdx.x * 2048u;
    {
        const unsigned i0 = compact3(baseCTA);
        const unsigned j0 = compact3(baseCTA >> 1);
        const unsigned k0 = compact3(baseCTA >> 2);
        if (tid < n_cams * NCASC) {
            const int cam = tid / NCASC;
            const int c = tid - cam * NCASC;
            const float4* c4 = s_cc + cam * C4;
            const float4 m0 = c4[0], m1 = c4[1], m2 = c4[2], m3 = c4[3];
            const float W = m3.z, H = m3.w;

            const float inv127 = 2.0f / 127.0f;
            const float xc = ((float)i0 + 7.5f) * inv127 - 1.0f;
            const float yc = ((float)j0 + 7.5f) * inv127 - 1.0f;
            const float zc = ((float)k0 + 3.5f) * inv127 - 1.0f;
            const float ex = 15.0f / 127.0f, ey = 15.0f / 127.0f, ez = 7.0f / 127.0f;

            const float p0 = m0.x * xc + m0.y * yc + m0.z * zc;
            const float p1 = m1.x * xc + m1.y * yc + m1.z * zc;
            const float p2 = m2.x * xc + m2.y * yc + m2.z * zc;
            const float r0 = p0 - W * p2;
            const float r1 = p1 - H * p2;

            const float INFL = 1.001f, EPSA = 0.03f;
            const float Rr0 = (fabsf(m0.x) * ex + fabsf(m0.y) * ey + fabsf(m0.z) * ez) * INFL + EPSA;
            const float Rr1 = (fabsf(m1.x) * ex + fabsf(m1.y) * ey + fabsf(m1.z) * ez) * INFL + EPSA;
            const float Rr2 = (fabsf(m2.x) * ex + fabsf(m2.y) * ey + fabsf(m2.z) * ez) * INFL + EPSA;
            const float g0x = m0.x - W * m2.x, g0y = m0.y - W * m2.y, g0z = m0.z - W * m2.z;
            const float g1x = m1.x - H * m2.x, g1y = m1.y - H * m2.y, g1z = m1.z - H * m2.z;
            const float Rr3 = (fabsf(g0x) * ex + fabsf(g0y) * ey + fabsf(g0z) * ez) * INFL + EPSA;
            const float Rr4 = (fabsf(g1x) * ex + fabsf(g1y) * ey + fabsf(g1z) * ez) * INFL + EPSA;

            const float4 v0 = c4[4 + 4 * c + 0];
            const float4 v1 = c4[4 + 4 * c + 1];
            bool allin  = (p0 >= v0.x + Rr0) & (r0 < v0.y - Rr3) & (p1 >= v0.z + Rr1) &
                          (r1 < v0.w - Rr4) & (p2 >= v1.x + Rr2);
            bool allout = (p0 < v0.x - Rr0) | (r0 >= v0.y + Rr3) | (p1 < v0.z - Rr1) |
                          (r1 >= v0.w + Rr4) | (p2 <= v1.y - Rr2);
            if (allin) atomicAdd(&s_allin[c], 1);
            else if (!allout) atomicOr(&s_bnd[cam], 1 << c);
        }
    }
    __syncthreads();
    if (tid == 0) {
        int n = 0;
        for (int i = 0; i < n_cams; i++)
            if (s_bnd[i]) s_camList[n++] = i;
        s_nBnd = n;
    }
    __syncthreads();

    // ---- Phase 3: per-thread (2x2x2) processing of CTA-boundary cams ----
    const unsigned base = baseCTA + (unsigned)tid * 8u;
    const unsigned ib = compact3(base);
    const unsigned jb = compact3(base >> 1);
    const unsigned kb = compact3(base >> 2);

    float xs[2], ys[2], zs[2];
#pragma unroll
    for (int d = 0; d < 2; d++) {
        xs[d] = __fdiv_rn((float)(ib + d), (float)(GG - 1)) * 2.0f - 1.0f;
        ys[d] = __fdiv_rn((float)(jb + d), (float)(GG - 1)) * 2.0f - 1.0f;
        zs[d] = __fdiv_rn((float)(kb + d), (float)(GG - 1)) * 2.0f - 1.0f;
    }
    const float xc = 0.5f * (xs[0] + xs[1]);
    const float yc = 0.5f * (ys[0] + ys[1]);
    const float zc = 0.5f * (zs[0] + zs[1]);
    const float W = s_cc[3].z, H = s_cc[3].w;

    unsigned acc[8];
#pragma unroll
    for (int i = 0; i < 8; i++) acc[i] = 0u;
    unsigned cntThr = 0u;

    const int nBnd = s_nBnd;
    for (int idx = 0; idx < nBnd; idx++) {
        const int cam = s_camList[idx];
        unsigned bm = (unsigned)s_bnd[cam];
        const float4* c4 = s_cc + cam * C4;
        const float4 m0 = c4[0], m1 = c4[1], m2 = c4[2];

        const float p0 = fmaf(m0.z, zc, fmaf(m0.y, yc, m0.x * xc));
        const float p1 = fmaf(m1.z, zc, fmaf(m1.y, yc, m1.x * xc));
        const float p2 = fmaf(m2.z, zc, fmaf(m2.y, yc, m2.x * xc));
        const float r0 = fmaf(-W, p2, p0);
        const float r1 = fmaf(-H, p2, p1);

        while (bm) {
            const int c = __ffs(bm) - 1;
            bm &= bm - 1;
            const float4 vef  = c4[4 + 4 * c + 1];
            const float4 vin  = c4[4 + 4 * c + 2];
            const float4 vout = c4[4 + 4 * c + 3];
            bool allin  = (p0 >= vin.x) & (r0 < vin.y) & (p1 >= vin.z) &
                          (r1 < vin.w) & (p2 >= vef.z);
            bool allout = (p0 < vout.x) | (r0 >= vout.y) | (p1 < vout.z) |
                          (r1 >= vout.w) | (p2 <= vef.w);
            if (allin) { cntThr += (1u << (5 * c)); continue; }
            if (allout) continue;

            // exact per-cell path (identical math to reference thresholds)
            const float4 v0 = c4[4 + 4 * c + 0];
            const unsigned covbit = 1u << (5 * c);
            const unsigned nearbit = 1u << (25 + c);
#pragma unroll
            for (int cell = 0; cell < 8; cell++) {
                const float x = xs[cell & 1];
                const float y = ys[(cell >> 1) & 1];
                const float z = zs[(cell >> 2) & 1];
                const float P0 = fmaf(m0.z, z, fmaf(m0.y, y, m0.x * x));
                const float P1 = fmaf(m1.z, z, fmaf(m1.y, y, m1.x * x));
                const float P2 = fmaf(m2.z, z, fmaf(m2.y, y, m2.x * x));
                const float R0 = fmaf(-W, P2, P0);
                const float R1 = fmaf(-H, P2, P1);
                bool i4 = (P0 >= v0.x) & (R0 < v0.y) & (P1 >= v0.z) & (R1 < v0.w);
                if (i4 & (P2 >= vef.x)) acc[cell] += covbit;
                if (i4 & (P2 < vef.x) & (P2 > vef.y)) acc[cell] |= nearbit;
            }
        }
    }

    // ---- Phase 4: epilogue ----
    const float invN = __fdiv_rn(1.0f, (float)n_cams);
    float* outg = out;
    float* outc = out + (size_t)NCASC * G3;

#pragma unroll
    for (int c = 0; c < NCASC; c++) {
        const unsigned allc = (unsigned)s_allin[c] + ((cntThr >> (5 * c)) & 31u);
        float gv[8], cv[8];
#pragma unroll
        for (int cell = 0; cell < 8; cell++) {
            unsigned cnt   = ((acc[cell] >> (5 * c)) & 31u) + allc;
            unsigned nearf = (acc[cell] >> (25 + c)) & 1u;
            cv[cell] = (float)cnt * invN;
            gv[cell] = (cnt > 0u && nearf == 0u) ? 0.0f : -1.0f;
        }
        size_t off = (size_t)c * G3 + base;
        float4* pg = (float4*)(outg + off);
        pg[0] = make_float4(gv[0], gv[1], gv[2], gv[3]);
        pg[1] = make_float4(gv[4], gv[5], gv[6], gv[7]);
        float4* pc = (float4*)(outc + off);
        pc[0] = make_float4(cv[0], cv[1], cv[2], cv[3]);
        pc[1] = make_float4(cv[4], cv[5], cv[6], cv[7]);
    }
}

extern "C" void kernel_launch(void* const* d_in, const int* in_sizes, int n_in,
                              void* d_out, int out_size)
{
    const float* K     = (const float*)d_in[0];
    const float* poses = (const float*)d_in[1];
    const int*   sc    = (const int*)d_in[3];
    const int*   wp    = (const int*)d_in[4];
    const int*   hp    = (const int*)d_in[5];

    int n_cams = in_sizes[1] / 12;
    if (n_cams > MAXCAMS) n_cams = MAXCAMS;

    const int threads = 256;
    const int blocks = (G3 / 8) / threads;  // 1024
    grid_kernel<<<blocks, threads>>>((float*)d_out, K, poses, sc, wp, hp, n_cams);
}

// round 8
// speedup vs baseline: 2.7346x; 1.1480x over previous
#include <cuda_runtime.h>

#define GG 128
#define G3 (GG * GG * GG)
#define NCASC 5
#define MAXCAMS 32
#define C4 24  // float4 per camera constant block

// Per-cam constants (float4 units) in shared memory, built in-kernel:
// [0] = (M00,M01,M02, rad0t)   thread-level interval radii in .w
// [1] = (M10,M11,M12, rad1t)
// [2] = (M20,M21,M22, rad2t)
// [3] = (rad3t, rad4t, W, H)
// per cascade c (base = 4+4c):
// [base+0] = (A, B, C, D)      exact thresholds (per-cell path)
// [base+1] = (E, F, E_in, F_out)
// [base+2] = (A_in, B_in, C_in, D_in)    thread-level all-in
// [base+3] = (A_out, B_out, C_out, D_out) thread-level all-out

__device__ __forceinline__ unsigned compact3(unsigned x) {
    x &= 0x49249249u;
    x = (x | (x >> 2))  & 0xC30C30C3u;
    x = (x | (x >> 4))  & 0x0F00F00Fu;
    x = (x | (x >> 8))  & 0xFF0000FFu;
    x = (x | (x >> 16)) & 0x000003FFu;
    return x;
}

#define NTHREADS 128
#define CELLS_PER_CTA 1024u   // 16 x 8 x 8 region (x:4 bits, y:3, z:3)

__global__ void __launch_bounds__(NTHREADS, 6)
grid_kernel(float* __restrict__ out,
            const float* __restrict__ K,
            const float* __restrict__ poses,
            const int* __restrict__ scale_p,
            const int* __restrict__ wp,
            const int* __restrict__ hp,
            int n_cams)
{
    __shared__ float4 s_cc[MAXCAMS * C4];
    __shared__ int s_allin[NCASC];
    __shared__ int s_bnd[MAXCAMS];
    __shared__ int s_camList[MAXCAMS];
    __shared__ int s_nBnd;

    const int tid = threadIdx.x;
    if (tid < NCASC) s_allin[tid] = 0;
    if (tid < MAXCAMS) s_bnd[tid] = 0;

    // ---- Phase 1: per-cam constant precompute (fp32, one thread per cam) ----
    if (tid < n_cams) {
        const float fx = K[0], cx = K[2], fy = K[4], cy = K[5];
        const float W = (float)(*wp), H = (float)(*hp);
        const float scal = (float)(*scale_p);

        const float* P = poses + tid * 12;
        const float R00 = P[0], R01 = P[1], R02 = P[2],  t0 = P[3];
        const float R10 = P[4], R11 = P[5], R12 = P[6],  t1 = P[7];
        const float R20 = P[8], R21 = P[9], R22 = P[10], t2 = P[11];
        // T' = -R^T t
        const float Tp0 = -(R00 * t0 + R10 * t1 + R20 * t2);
        const float Tp1 = -(R01 * t0 + R11 * t1 + R21 * t2);
        const float Tp2 = -(R02 * t0 + R12 * t1 + R22 * t2);
        // M = K @ R^T rows
        const float M00 = fx * R00 + cx * R02, M01 = fx * R10 + cx * R12, M02 = fx * R20 + cx * R22;
        const float M10 = fy * R01 + cy * R02, M11 = fy * R11 + cy * R12, M12 = fy * R21 + cy * R22;
        const float M20 = R02, M21 = R12, M22 = R22;
        const float q0 = fx * Tp0 + cx * Tp2;
        const float q1 = fy * Tp1 + cy * Tp2;
        const float q2 = Tp2;

        // thread-level (2x2x2 block) interval radii, conservative
        const float h = 1.0f / (float)(GG - 1);
        const float INFL = 1.001f, EPSA = 0.03f;
        const float rad0 = (fabsf(M00) + fabsf(M01) + fabsf(M02)) * h * INFL + EPSA;
        const float rad1 = (fabsf(M10) + fabsf(M11) + fabsf(M12)) * h * INFL + EPSA;
        const float rad2 = (fabsf(M20) + fabsf(M21) + fabsf(M22)) * h * INFL + EPSA;
        const float rad3 = (fabsf(M00 - W * M20) + fabsf(M01 - W * M21) +
                            fabsf(M02 - W * M22)) * h * INFL + EPSA;
        const float rad4 = (fabsf(M10 - H * M20) + fabsf(M11 - H * M21) +
                            fabsf(M12 - H * M22)) * h * INFL + EPSA;

        float4* cc = s_cc + tid * C4;
        cc[0] = make_float4(M00, M01, M02, rad0);
        cc[1] = make_float4(M10, M11, M12, rad1);
        cc[2] = make_float4(M20, M21, M22, rad2);
        cc[3] = make_float4(rad3, rad4, W, H);

#pragma unroll
        for (int c = 0; c < NCASC; c++) {
            float s = fminf(exp2f((float)(c - 1)), scal);
            float se = s - s * (1.0f / (float)GG);   // exact: powers of two
            float inv = __fdiv_rn(1.0f, se);
            float A = -q0 * inv;
            float B = (W * q2 - q0) * inv;
            float C = -q1 * inv;
            float D = (H * q2 - q1) * inv;
            float E = (0.01f - q2) * inv;
            float F = -q2 * inv;
            cc[4 + 4 * c + 0] = make_float4(A, B, C, D);
            cc[4 + 4 * c + 1] = make_float4(E, F, E + rad2, F - rad2);
            cc[4 + 4 * c + 2] = make_float4(A + rad0, B - rad3, C + rad1, D - rad4);
            cc[4 + 4 * c + 3] = make_float4(A - rad0, B + rad3, C - rad1, D + rad4);
        }
    }
    __syncthreads();

    // ---- Phase 2: CTA-level classification (region = 16x8x8 cells) ----
    const unsigned baseCTA = blockIdx.x * CELLS_PER_CTA;
    {
        const unsigned i0 = compact3(baseCTA);
        const unsigned j0 = compact3(baseCTA >> 1);
        const unsigned k0 = compact3(baseCTA >> 2);
        if (tid < n_cams * NCASC) {
            const int cam = tid / NCASC;
            const int c = tid - cam * NCASC;
            const float4* c4 = s_cc + cam * C4;
            const float4 m0 = c4[0], m1 = c4[1], m2 = c4[2], m3 = c4[3];
            const float W = m3.z, H = m3.w;

            const float inv127 = 2.0f / 127.0f;
            const float xc = ((float)i0 + 7.5f) * inv127 - 1.0f;
            const float yc = ((float)j0 + 3.5f) * inv127 - 1.0f;
            const float zc = ((float)k0 + 3.5f) * inv127 - 1.0f;
            const float ex = 15.0f / 127.0f, ey = 7.0f / 127.0f, ez = 7.0f / 127.0f;

            const float p0 = m0.x * xc + m0.y * yc + m0.z * zc;
            const float p1 = m1.x * xc + m1.y * yc + m1.z * zc;
            const float p2 = m2.x * xc + m2.y * yc + m2.z * zc;
            const float r0 = p0 - W * p2;
            const float r1 = p1 - H * p2;

            const float INFL = 1.001f, EPSA = 0.03f;
            const float Rr0 = (fabsf(m0.x) * ex + fabsf(m0.y) * ey + fabsf(m0.z) * ez) * INFL + EPSA;
            const float Rr1 = (fabsf(m1.x) * ex + fabsf(m1.y) * ey + fabsf(m1.z) * ez) * INFL + EPSA;
            const float Rr2 = (fabsf(m2.x) * ex + fabsf(m2.y) * ey + fabsf(m2.z) * ez) * INFL + EPSA;
            const float g0x = m0.x - W * m2.x, g0y = m0.y - W * m2.y, g0z = m0.z - W * m2.z;
            const float g1x = m1.x - H * m2.x, g1y = m1.y - H * m2.y, g1z = m1.z - H * m2.z;
            const float Rr3 = (fabsf(g0x) * ex + fabsf(g0y) * ey + fabsf(g0z) * ez) * INFL + EPSA;
            const float Rr4 = (fabsf(g1x) * ex + fabsf(g1y) * ey + fabsf(g1z) * ez) * INFL + EPSA;

            const float4 v0 = c4[4 + 4 * c + 0];
            const float4 v1 = c4[4 + 4 * c + 1];
            bool allin  = (p0 >= v0.x + Rr0) & (r0 < v0.y - Rr3) & (p1 >= v0.z + Rr1) &
                          (r1 < v0.w - Rr4) & (p2 >= v1.x + Rr2);
            bool allout = (p0 < v0.x - Rr0) | (r0 >= v0.y + Rr3) | (p1 < v0.z - Rr1) |
                          (r1 >= v0.w + Rr4) | (p2 <= v1.y - Rr2);
            if (allin) atomicAdd(&s_allin[c], 1);
            else if (!allout) atomicOr(&s_bnd[cam], 1 << c);
        }
    }
    __syncthreads();
    if (tid == 0) {
        int n = 0;
        for (int i = 0; i < n_cams; i++)
            if (s_bnd[i]) s_camList[n++] = i;
        s_nBnd = n;
    }
    __syncthreads();

    // ---- Phase 3: per-thread (2x2x2) processing of CTA-boundary cams ----
    const unsigned base = baseCTA + (unsigned)tid * 8u;
    const unsigned ib = compact3(base);
    const unsigned jb = compact3(base >> 1);
    const unsigned kb = compact3(base >> 2);

    float xs[2], ys[2], zs[2];
#pragma unroll
    for (int d = 0; d < 2; d++) {
        xs[d] = __fdiv_rn((float)(ib + d), (float)(GG - 1)) * 2.0f - 1.0f;
        ys[d] = __fdiv_rn((float)(jb + d), (float)(GG - 1)) * 2.0f - 1.0f;
        zs[d] = __fdiv_rn((float)(kb + d), (float)(GG - 1)) * 2.0f - 1.0f;
    }
    const float xc = 0.5f * (xs[0] + xs[1]);
    const float yc = 0.5f * (ys[0] + ys[1]);
    const float zc = 0.5f * (zs[0] + zs[1]);
    const float W = s_cc[3].z, H = s_cc[3].w;

    unsigned acc[8];
#pragma unroll
    for (int i = 0; i < 8; i++) acc[i] = 0u;
    unsigned cntThr = 0u;

    const int nBnd = s_nBnd;
    for (int idx = 0; idx < nBnd; idx++) {
        const int cam = s_camList[idx];
        const unsigned bm = (unsigned)s_bnd[cam];
        const float4* c4 = s_cc + cam * C4;
        const float4 m0 = c4[0], m1 = c4[1], m2 = c4[2];

        const float p0 = fmaf(m0.z, zc, fmaf(m0.y, yc, m0.x * xc));
        const float p1 = fmaf(m1.z, zc, fmaf(m1.y, yc, m1.x * xc));
        const float p2 = fmaf(m2.z, zc, fmaf(m2.y, yc, m2.x * xc));
        const float r0 = fmaf(-W, p2, p0);
        const float r1 = fmaf(-H, p2, p1);

#pragma unroll
        for (int c = 0; c < NCASC; c++) {
            if (!((bm >> c) & 1u)) continue;
            const float4 vef  = c4[4 + 4 * c + 1];
            const float4 vin  = c4[4 + 4 * c + 2];
            const float4 vout = c4[4 + 4 * c + 3];
            bool allin  = (p0 >= vin.x) & (r0 < vin.y) & (p1 >= vin.z) &
                          (r1 < vin.w) & (p2 >= vef.z);
            bool allout = (p0 < vout.x) | (r0 >= vout.y) | (p1 < vout.z) |
                          (r1 >= vout.w) | (p2 <= vef.w);
            if (allin) { cntThr += (1u << (5 * c)); continue; }
            if (allout) continue;

            // exact per-cell path (identical math to reference thresholds)
            const float4 v0 = c4[4 + 4 * c + 0];
            const unsigned covbit = 1u << (5 * c);
            const unsigned nearbit = 1u << (25 + c);
#pragma unroll
            for (int cell = 0; cell < 8; cell++) {
                const float x = xs[cell & 1];
                const float y = ys[(cell >> 1) & 1];
                const float z = zs[(cell >> 2) & 1];
                const float P0 = fmaf(m0.z, z, fmaf(m0.y, y, m0.x * x));
                const float P1 = fmaf(m1.z, z, fmaf(m1.y, y, m1.x * x));
                const float P2 = fmaf(m2.z, z, fmaf(m2.y, y, m2.x * x));
                const float R0 = fmaf(-W, P2, P0);
                const float R1 = fmaf(-H, P2, P1);
                bool i4 = (P0 >= v0.x) & (R0 < v0.y) & (P1 >= v0.z) & (R1 < v0.w);
                if (i4 & (P2 >= vef.x)) acc[cell] += covbit;
                if (i4 & (P2 < vef.x) & (P2 > vef.y)) acc[cell] |= nearbit;
            }
        }
    }

    // ---- Phase 4: epilogue ----
    const float invN = __fdiv_rn(1.0f, (float)n_cams);
    float* outg = out;
    float* outc = out + (size_t)NCASC * G3;

    unsigned any = 0u;
#pragma unroll
    for (int i = 0; i < 8; i++) any |= acc[i];

    if (any == 0u) {
        // uniform fast path: all 8 cells share one value per cascade
#pragma unroll
        for (int c = 0; c < NCASC; c++) {
            const unsigned cnt = (unsigned)s_allin[c] + ((cntThr >> (5 * c)) & 31u);
            const float cv = (float)cnt * invN;
            const float gv = (cnt > 0u) ? 0.0f : -1.0f;
            size_t off = (size_t)c * G3 + base;
            float4* pg = (float4*)(outg + off);
            float4 g4 = make_float4(gv, gv, gv, gv);
            pg[0] = g4; pg[1] = g4;
            float4* pc = (float4*)(outc + off);
            float4 c4v = make_float4(cv, cv, cv, cv);
            pc[0] = c4v; pc[1] = c4v;
        }
    } else {
#pragma unroll
        for (int c = 0; c < NCASC; c++) {
            const unsigned allc = (unsigned)s_allin[c] + ((cntThr >> (5 * c)) & 31u);
            float gv[8], cv[8];
#pragma unroll
            for (int cell = 0; cell < 8; cell++) {
                unsigned cnt   = ((acc[cell] >> (5 * c)) & 31u) + allc;
                unsigned nearf = (acc[cell] >> (25 + c)) & 1u;
                cv[cell] = (float)cnt * invN;
                gv[cell] = (cnt > 0u && nearf == 0u) ? 0.0f : -1.0f;
            }
            size_t off = (size_t)c * G3 + base;
            float4* pg = (float4*)(outg + off);
            pg[0] = make_float4(gv[0], gv[1], gv[2], gv[3]);
            pg[1] = make_float4(gv[4], gv[5], gv[6], gv[7]);
            float4* pc = (float4*)(outc + off);
            pc[0] = make_float4(cv[0], cv[1], cv[2], cv[3]);
            pc[1] = make_float4(cv[4], cv[5], cv[6], cv[7]);
        }
    }
}

extern "C" void kernel_launch(void* const* d_in, const int* in_sizes, int n_in,
                              void* d_out, int out_size)
{
    const float* K     = (const float*)d_in[0];
    const float* poses = (const float*)d_in[1];
    const int*   sc    = (const int*)d_in[3];
    const int*   wp    = (const int*)d_in[4];
    const int*   hp    = (const int*)d_in[5];

    int n_cams = in_sizes[1] / 12;
    if (n_cams > MAXCAMS) n_cams = MAXCAMS;

    const int blocks = G3 / (int)CELLS_PER_CTA;  // 2048
    grid_kernel<<<blocks, NTHREADS>>>((float*)d_out, K, poses, sc, wp, hp, n_cams);
}